// round 14
// baseline (speedup 1.0000x reference)
#include <cuda_runtime.h>
#include <cuda_bf16.h>
#include <math.h>

// Problem constants
#define BATCH 2
#define HEADS 12
#define DHEAD 64
#define NCTX  2048
#define DMODEL 768
#define MROWS (BATCH * NCTX)          // 4096
#define BHPD  (BATCH * HEADS * NCTX * DHEAD)   // 3,145,728

// Scratch (device globals: no allocation allowed)
__device__ float g_Q[BHPD];
__device__ float g_K[BHPD];
__device__ float g_V[BHPD];
__device__ float g_Z[MROWS * DMODEL];

// ---------------------------------------------------------------------------
// SGEMM core: C[m][n] = sum_k A[m][k] * B[n][k]  (both operands K-contiguous)
// BM=BN=128, BK=16, 256 threads, 8x8 per-thread micro-tile.
// Double-buffered smem: one __syncthreads per K-tile, LDG overlapped with FMA.
// Epilogue uses STG.128 (j-groups of 8 are memory-contiguous in both modes).
// MODE 0: C row-major [M][N]
// MODE 1: QKV scatter -> [B, H, P, DHEAD]  (m = b*NCTX+p, n = h*DHEAD+e)
// ---------------------------------------------------------------------------
#define BM 128
#define BN 128
#define BK 16
#define LDA (BM + 4)
#define STAGE (BK * LDA)              // floats per stage per operand

template <int MODE>
__device__ __forceinline__ void sgemm_body(
    const float* __restrict__ A, const float* __restrict__ B,
    float* __restrict__ C, int M, int N, int K)
{
    extern __shared__ float smem[];
    float* As = smem;                  // [2][BK][LDA]
    float* Bs = smem + 2 * STAGE;      // [2][BK][LDA]

    const int tid = threadIdx.x;
    const int bm = blockIdx.x * BM;
    const int bn = blockIdx.y * BN;
    const int tx = tid & 15;        // 0..15 (N direction)
    const int ty = tid >> 4;        // 0..15 (M direction)

    float acc[8][8];
#pragma unroll
    for (int i = 0; i < 8; i++)
#pragma unroll
        for (int j = 0; j < 8; j++) acc[i][j] = 0.0f;

    const int lr = tid >> 2;          // 0..63
    const int lc = (tid & 3) * 4;     // 0,4,8,12
    const float* Ap = A + (size_t)(bm + lr) * K + lc;
    const float* Bp = B + (size_t)(bn + lr) * K + lc;

    const int T = K / BK;             // 48 for K=768

    // --- prologue: load tile 0 into stage 0 ---
    {
        float4 a0 = *(const float4*)(Ap);
        float4 a1 = *(const float4*)(Ap + (size_t)64 * K);
        float4 b0 = *(const float4*)(Bp);
        float4 b1 = *(const float4*)(Bp + (size_t)64 * K);
        float* Ad = As;
        float* Bd = Bs;
        Ad[(lc + 0) * LDA + lr]      = a0.x; Ad[(lc + 1) * LDA + lr]      = a0.y;
        Ad[(lc + 2) * LDA + lr]      = a0.z; Ad[(lc + 3) * LDA + lr]      = a0.w;
        Ad[(lc + 0) * LDA + lr + 64] = a1.x; Ad[(lc + 1) * LDA + lr + 64] = a1.y;
        Ad[(lc + 2) * LDA + lr + 64] = a1.z; Ad[(lc + 3) * LDA + lr + 64] = a1.w;
        Bd[(lc + 0) * LDA + lr]      = b0.x; Bd[(lc + 1) * LDA + lr]      = b0.y;
        Bd[(lc + 2) * LDA + lr]      = b0.z; Bd[(lc + 3) * LDA + lr]      = b0.w;
        Bd[(lc + 0) * LDA + lr + 64] = b1.x; Bd[(lc + 1) * LDA + lr + 64] = b1.y;
        Bd[(lc + 2) * LDA + lr + 64] = b1.z; Bd[(lc + 3) * LDA + lr + 64] = b1.w;
    }
    __syncthreads();

    int buf = 0;
    for (int t = 0; t < T; t++) {
        // prefetch next tile's GMEM into registers (latency hidden by compute)
        float4 a0, a1, b0, b1;
        const bool have_next = (t + 1 < T);
        if (have_next) {
            const int k0 = (t + 1) * BK;
            a0 = *(const float4*)(Ap + k0);
            a1 = *(const float4*)(Ap + (size_t)64 * K + k0);
            b0 = *(const float4*)(Bp + k0);
            b1 = *(const float4*)(Bp + (size_t)64 * K + k0);
        }

        // compute on current stage
        const float* Ac = As + buf * STAGE;
        const float* Bc = Bs + buf * STAGE;
#pragma unroll
        for (int kk = 0; kk < BK; kk++) {
            float ra[8], rb[8];
            *(float4*)(ra)     = *(const float4*)&Ac[kk * LDA + ty * 8];
            *(float4*)(ra + 4) = *(const float4*)&Ac[kk * LDA + ty * 8 + 4];
            *(float4*)(rb)     = *(const float4*)&Bc[kk * LDA + tx * 8];
            *(float4*)(rb + 4) = *(const float4*)&Bc[kk * LDA + tx * 8 + 4];
#pragma unroll
            for (int i = 0; i < 8; i++)
#pragma unroll
                for (int j = 0; j < 8; j++)
                    acc[i][j] = fmaf(ra[i], rb[j], acc[i][j]);
        }

        // store prefetched tile into the other stage
        if (have_next) {
            float* Ad = As + (buf ^ 1) * STAGE;
            float* Bd = Bs + (buf ^ 1) * STAGE;
            Ad[(lc + 0) * LDA + lr]      = a0.x; Ad[(lc + 1) * LDA + lr]      = a0.y;
            Ad[(lc + 2) * LDA + lr]      = a0.z; Ad[(lc + 3) * LDA + lr]      = a0.w;
            Ad[(lc + 0) * LDA + lr + 64] = a1.x; Ad[(lc + 1) * LDA + lr + 64] = a1.y;
            Ad[(lc + 2) * LDA + lr + 64] = a1.z; Ad[(lc + 3) * LDA + lr + 64] = a1.w;
            Bd[(lc + 0) * LDA + lr]      = b0.x; Bd[(lc + 1) * LDA + lr]      = b0.y;
            Bd[(lc + 2) * LDA + lr]      = b0.z; Bd[(lc + 3) * LDA + lr]      = b0.w;
            Bd[(lc + 0) * LDA + lr + 64] = b1.x; Bd[(lc + 1) * LDA + lr + 64] = b1.y;
            Bd[(lc + 2) * LDA + lr + 64] = b1.z; Bd[(lc + 3) * LDA + lr + 64] = b1.w;
        }
        __syncthreads();
        buf ^= 1;
    }

    // --- epilogue: two STG.128 per row (j-group of 8 is contiguous in both modes) ---
    const int n0 = bn + tx * 8;
#pragma unroll
    for (int i = 0; i < 8; i++) {
        const int m = bm + ty * 8 + i;
        float4 lo = make_float4(acc[i][0], acc[i][1], acc[i][2], acc[i][3]);
        float4 hi = make_float4(acc[i][4], acc[i][5], acc[i][6], acc[i][7]);
        if (MODE == 0) {
            float4* dst = (float4*)&C[(size_t)m * N + n0];
            dst[0] = lo;
            dst[1] = hi;
        } else {
            const int b = m >> 11;          // / NCTX
            const int p = m & (NCTX - 1);
            const int h = n0 >> 6;          // / DHEAD (constant over the 8-group)
            const int e = n0 & (DHEAD - 1); // contiguous e..e+7
            float4* dst = (float4*)&C[(((size_t)(b * HEADS + h)) * NCTX + p) * DHEAD + e];
            dst[0] = lo;
            dst[1] = hi;
        }
    }
}

// Fused QKV: gridDim.z selects which projection this CTA computes.
__global__ void __launch_bounds__(256)
qkv_gemm(const float* __restrict__ x,
         const float* __restrict__ Wq, const float* __restrict__ Wk,
         const float* __restrict__ Wv,
         float* __restrict__ Cq, float* __restrict__ Ck, float* __restrict__ Cv)
{
    const float* W = (blockIdx.z == 0) ? Wq : (blockIdx.z == 1) ? Wk : Wv;
    float* C       = (blockIdx.z == 0) ? Cq : (blockIdx.z == 1) ? Ck : Cv;
    sgemm_body<1>(x, W, C, MROWS, DMODEL, DMODEL);
}

__global__ void __launch_bounds__(256)
out_gemm(const float* __restrict__ A, const float* __restrict__ B,
         float* __restrict__ C)
{
    sgemm_body<0>(A, B, C, MROWS, DMODEL, DMODEL);
}

#define SGEMM_SMEM (4 * STAGE * (int)sizeof(float))   // 2 ops x 2 stages = 33792 B

// ---------------------------------------------------------------------------
// Flash attention (fp32, causal). One CTA = 64 query rows of one (b,h).
// 256 threads as 16(ty:rows) x 16(tx:cols); each thread: 4 rows x 4 cols.
// Q stored TRANSPOSED in smem (Qt[d][r]) so both S-loop operands are LDS.128.
// K/V tiles are register-staged one iteration ahead: LDG issued right after
// the tiles-visible barrier, consumed at the top of the NEXT iteration, so
// GMEM latency hides behind the full S/softmax/O compute body.
// Writes head-major z_flat[b][p][h*64+e] directly.
// ---------------------------------------------------------------------------
#define SQ 68     // smem row stride (floats): multiple of 4, conflict-free
#define QSCALE 0.125f   // 1/sqrt(64)

__global__ void __launch_bounds__(256)
flash_kernel(const float* __restrict__ Qg, const float* __restrict__ Kg,
             const float* __restrict__ Vg, float* __restrict__ Z)
{
    extern __shared__ float sm[];
    float* Qt = sm;                 // [64][SQ]  dim d, row r   (transposed)
    float* Kt = sm + 64 * SQ;       // [64][SQ]  dim d, key n   (transposed)
    float* Vs = sm + 2 * 64 * SQ;   // [64][SQ]  key n, dim d
    float* Ps = sm + 3 * 64 * SQ;   // [64][SQ]  row r, key n

    const int bh = blockIdx.y;
    const int b = bh / HEADS;
    const int h = bh - b * HEADS;
    const int qb = (int)gridDim.x - 1 - (int)blockIdx.x;   // heavy blocks first
    const int q0 = qb * 64;

    const float* Qb = Qg + (size_t)bh * NCTX * DHEAD;
    const float* Kb = Kg + (size_t)bh * NCTX * DHEAD;
    const float* Vb = Vg + (size_t)bh * NCTX * DHEAD;

    const int tid = threadIdx.x;
    const int tx = tid & 15;
    const int ty = tid >> 4;
    const int lr = tid >> 2;          // 0..63
    const int lc = (tid & 3) * 16;    // 0,16,32,48

    // Load Q tile (scaled), transposed into Qt[d][r]
    {
        const float4* src = (const float4*)(Qb + (size_t)(q0 + lr) * DHEAD + lc);
#pragma unroll
        for (int v = 0; v < 4; v++) {
            float4 q4 = src[v];
            const int c = lc + v * 4;
            Qt[(c + 0) * SQ + lr] = q4.x * QSCALE;
            Qt[(c + 1) * SQ + lr] = q4.y * QSCALE;
            Qt[(c + 2) * SQ + lr] = q4.z * QSCALE;
            Qt[(c + 3) * SQ + lr] = q4.w * QSCALE;
        }
    }

    float acc[4][4];
    float mrow[4], lrow[4];
#pragma unroll
    for (int i = 0; i < 4; i++) {
        mrow[i] = -1e30f; lrow[i] = 0.0f;
#pragma unroll
        for (int j = 0; j < 4; j++) acc[i][j] = 0.0f;
    }

    // prologue: register-stage K/V tile 0
    float4 kr[4], vr[4];
    {
        const float4* ks = (const float4*)(Kb + (size_t)lr * DHEAD + lc);
        const float4* vs = (const float4*)(Vb + (size_t)lr * DHEAD + lc);
#pragma unroll
        for (int v = 0; v < 4; v++) { kr[v] = ks[v]; vr[v] = vs[v]; }
    }

    for (int kb = 0; kb <= qb; kb++) {
        // commit staged registers to smem (K transposed)
#pragma unroll
        for (int v = 0; v < 4; v++) {
            const int c = lc + v * 4;
            Kt[(c + 0) * SQ + lr] = kr[v].x;
            Kt[(c + 1) * SQ + lr] = kr[v].y;
            Kt[(c + 2) * SQ + lr] = kr[v].z;
            Kt[(c + 3) * SQ + lr] = kr[v].w;
            *(float4*)&Vs[lr * SQ + c] = vr[v];
        }
        __syncthreads();   // (A) tiles visible

        // issue next tile's loads now; consumed at next iteration's commit
        if (kb < qb) {
            const int nbase = (kb + 1) * 64;
            const float4* ks = (const float4*)(Kb + (size_t)(nbase + lr) * DHEAD + lc);
            const float4* vs = (const float4*)(Vb + (size_t)(nbase + lr) * DHEAD + lc);
#pragma unroll
            for (int v = 0; v < 4; v++) { kr[v] = ks[v]; vr[v] = vs[v]; }
        }

        // S = Q * K^T  (per-thread 4x4); both operands contiguous along r/n
        float s[4][4];
#pragma unroll
        for (int i = 0; i < 4; i++)
#pragma unroll
            for (int j = 0; j < 4; j++) s[i][j] = 0.0f;
#pragma unroll
        for (int kk = 0; kk < 64; kk++) {
            float qa[4], kv[4];
            *(float4*)qa = *(const float4*)&Qt[kk * SQ + ty * 4];
            *(float4*)kv = *(const float4*)&Kt[kk * SQ + tx * 4];
#pragma unroll
            for (int i = 0; i < 4; i++)
#pragma unroll
                for (int j = 0; j < 4; j++)
                    s[i][j] = fmaf(qa[i], kv[j], s[i][j]);
        }

        // causal mask on diagonal block
        if (kb == qb) {
            const int kbase = kb * 64;
#pragma unroll
            for (int i = 0; i < 4; i++) {
                const int qg = q0 + ty * 4 + i;
#pragma unroll
                for (int j = 0; j < 4; j++) {
                    if (kbase + tx * 4 + j > qg) s[i][j] = -1e30f;
                }
            }
        }

        // online softmax (row groups = 16 tx threads, width-16 shuffles)
#pragma unroll
        for (int i = 0; i < 4; i++) {
            float mx = fmaxf(fmaxf(s[i][0], s[i][1]), fmaxf(s[i][2], s[i][3]));
#pragma unroll
            for (int o = 8; o >= 1; o >>= 1)
                mx = fmaxf(mx, __shfl_xor_sync(0xffffffffu, mx, o, 16));
            const float mnew = fmaxf(mrow[i], mx);
            const float alpha = __expf(mrow[i] - mnew);
            float psum = 0.0f;
#pragma unroll
            for (int j = 0; j < 4; j++) {
                const float p = __expf(s[i][j] - mnew);
                s[i][j] = p;
                psum += p;
            }
#pragma unroll
            for (int o = 8; o >= 1; o >>= 1)
                psum += __shfl_xor_sync(0xffffffffu, psum, o, 16);
            lrow[i] = lrow[i] * alpha + psum;
            mrow[i] = mnew;
#pragma unroll
            for (int j = 0; j < 4; j++) acc[i][j] *= alpha;
        }

        // stage P to smem
#pragma unroll
        for (int i = 0; i < 4; i++)
            *(float4*)&Ps[(ty * 4 + i) * SQ + tx * 4] = *(float4*)s[i];
        __syncthreads();   // (B) Ps visible

        // O += P * V
#pragma unroll
        for (int kk = 0; kk < 64; kk++) {
            float pr[4];
#pragma unroll
            for (int i = 0; i < 4; i++) pr[i] = Ps[(ty * 4 + i) * SQ + kk];
            float vv[4];
            *(float4*)vv = *(const float4*)&Vs[kk * SQ + tx * 4];
#pragma unroll
            for (int i = 0; i < 4; i++)
#pragma unroll
                for (int j = 0; j < 4; j++)
                    acc[i][j] = fmaf(pr[i], vv[j], acc[i][j]);
        }
        __syncthreads();   // (C) Kt/Vs/Ps reads done before next commit
    }

    // epilogue: head-major z_flat[b][p][h*64+e]
#pragma unroll
    for (int i = 0; i < 4; i++) {
        const int p = q0 + ty * 4 + i;
        const float rinv = 1.0f / lrow[i];
        float4 o4;
        o4.x = acc[i][0] * rinv;
        o4.y = acc[i][1] * rinv;
        o4.z = acc[i][2] * rinv;
        o4.w = acc[i][3] * rinv;
        *(float4*)&Z[((size_t)(b * NCTX + p)) * DMODEL + h * DHEAD + tx * 4] = o4;
    }
}

// ---------------------------------------------------------------------------
// Host launcher
// ---------------------------------------------------------------------------
extern "C" void kernel_launch(void* const* d_in, const int* in_sizes, int n_in,
                              void* d_out, int out_size)
{
    const float* x   = (const float*)d_in[0];
    const float* W_K = (const float*)d_in[1];
    const float* W_Q = (const float*)d_in[2];
    const float* W_V = (const float*)d_in[3];
    const float* W_O = (const float*)d_in[4];
    float* out = (float*)d_out;
    (void)in_sizes; (void)n_in; (void)out_size;

    float *qp, *kp, *vp, *zp;
    cudaGetSymbolAddress((void**)&qp, g_Q);
    cudaGetSymbolAddress((void**)&kp, g_K);
    cudaGetSymbolAddress((void**)&vp, g_V);
    cudaGetSymbolAddress((void**)&zp, g_Z);

    const int FLASH_SMEM = 4 * 64 * SQ * (int)sizeof(float);   // 69632 B
    cudaFuncSetAttribute(flash_kernel,
                         cudaFuncAttributeMaxDynamicSharedMemorySize, FLASH_SMEM);

    dim3 ggrid(MROWS / BM, DMODEL / BN);          // (32, 6)
    dim3 qkvgrid(MROWS / BM, DMODEL / BN, 3);     // (32, 6, 3) = 576 CTAs

    // Fused QKV projections (scatter into [B,H,P,64])
    qkv_gemm<<<qkvgrid, 256, SGEMM_SMEM>>>(x, W_Q, W_K, W_V, qp, kp, vp);

    // Fused causal attention -> head-major z_flat
    flash_kernel<<<dim3(NCTX / 64, BATCH * HEADS), 256, FLASH_SMEM>>>(qp, kp, vp, zp);

    // Output projection
    out_gemm<<<ggrid, 256, SGEMM_SMEM>>>(zp, W_O, out);
}

// round 15
// speedup vs baseline: 1.1827x; 1.1827x over previous
#include <cuda_runtime.h>
#include <cuda_bf16.h>
#include <math.h>
#include <stdint.h>

// Problem constants
#define BATCH 2
#define HEADS 12
#define DHEAD 64
#define NCTX  2048
#define DMODEL 768
#define MROWS (BATCH * NCTX)          // 4096
#define BHPD  (BATCH * HEADS * NCTX * DHEAD)   // 3,145,728

// Scratch (device globals: no allocation allowed)
__device__ float g_Q[BHPD];
__device__ float g_K[BHPD];
__device__ float g_V[BHPD];
__device__ float g_Z[MROWS * DMODEL];

// ---------------------------------------------------------------------------
// Split-bf16 tensor-core GEMM: C[m][n] = sum_k A[m][k]*B[n][k], fp32 in/out.
// Each fp32 x is split x = hi + lo (hi = bf16(x), lo = bf16(x - hi)); the
// product uses 3 bf16 MMAs (hi*hi + hi*lo + lo*hi) accumulated in fp32
// (Ootomo split; dropped lo*lo term ~2^-18, rel err ~1e-5 << 1e-3 gate).
// Tile: BM=BN=128, BK=32, 256 threads (8 warps, 2x4), warp tile 64x32,
// mma.sync.aligned.m16n8k16.row.col.f32.bf16.bf16.f32.
// Double-buffered smem, register prefetch, one barrier per K-tile.
// MODE 0: C row-major.  MODE 1: QKV scatter -> [B,H,P,DHEAD].
// ---------------------------------------------------------------------------
#define GBM 128
#define GBN 128
#define GBK 32
#define KP 20                         // uint32 (bf16-pair) row stride: 16 data + 4 pad
#define HSTAGE (128 * KP)             // uint32 per matrix-half per stage
#define GSMEM_BYTES (2 * 4 * HSTAGE * 4)   // 2 stages x {Ahi,Alo,Bhi,Blo} = 81920 B

__device__ __forceinline__ uint32_t pack_bf2(float x, float y) {
    return ((uint32_t)__bfloat16_as_ushort(__float2bfloat16(y)) << 16)
         | (uint32_t)__bfloat16_as_ushort(__float2bfloat16(x));
}

__device__ __forceinline__ void mma16816(float* c, const uint32_t* a, const uint32_t* b) {
    asm volatile(
        "mma.sync.aligned.m16n8k16.row.col.f32.bf16.bf16.f32 "
        "{%0,%1,%2,%3}, {%4,%5,%6,%7}, {%8,%9}, {%0,%1,%2,%3};"
        : "+f"(c[0]), "+f"(c[1]), "+f"(c[2]), "+f"(c[3])
        : "r"(a[0]), "r"(a[1]), "r"(a[2]), "r"(a[3]), "r"(b[0]), "r"(b[1]));
}

// Split a 16-float row chunk into hi/lo bf16 pairs and store (two uint4 each).
__device__ __forceinline__ void split_store(uint32_t* __restrict__ Hhi,
                                            uint32_t* __restrict__ Hlo,
                                            int row, int pc, const float4* v)
{
    uint32_t hu[8], lu[8];
#pragma unroll
    for (int q = 0; q < 4; q++) {
        float4 t = v[q];
        float rx = t.x - __bfloat162float(__float2bfloat16(t.x));
        float ry = t.y - __bfloat162float(__float2bfloat16(t.y));
        float rz = t.z - __bfloat162float(__float2bfloat16(t.z));
        float rw = t.w - __bfloat162float(__float2bfloat16(t.w));
        hu[q * 2 + 0] = pack_bf2(t.x, t.y);
        hu[q * 2 + 1] = pack_bf2(t.z, t.w);
        lu[q * 2 + 0] = pack_bf2(rx, ry);
        lu[q * 2 + 1] = pack_bf2(rz, rw);
    }
    uint32_t* dh = Hhi + row * KP + pc;
    uint32_t* dl = Hlo + row * KP + pc;
    *(uint4*)(dh)     = make_uint4(hu[0], hu[1], hu[2], hu[3]);
    *(uint4*)(dh + 4) = make_uint4(hu[4], hu[5], hu[6], hu[7]);
    *(uint4*)(dl)     = make_uint4(lu[0], lu[1], lu[2], lu[3]);
    *(uint4*)(dl + 4) = make_uint4(lu[4], lu[5], lu[6], lu[7]);
}

template <int MODE>
__device__ __forceinline__ void bgemm_body(
    const float* __restrict__ A, const float* __restrict__ B,
    float* __restrict__ C, int M, int N, int K)
{
    extern __shared__ uint32_t smem32[];

    const int tid = threadIdx.x;
    const int bm = blockIdx.x * GBM;
    const int bn = blockIdx.y * GBN;

    const int wid  = tid >> 5;        // 0..7
    const int wm   = wid & 1;         // 2 warps along M
    const int wn   = wid >> 1;        // 4 warps along N
    const int lane = tid & 31;
    const int gid  = lane >> 2;       // 0..7
    const int tq   = lane & 3;        // 0..3

    const int lr  = tid >> 1;         // 0..127 (row within tile)
    const int pc  = (tid & 1) * 8;    // pair-column base (0 or 8)
    const int lcg = (tid & 1) * 16;   // float-column base (0 or 16)

    const float* Ap = A + (size_t)(bm + lr) * K + lcg;
    const float* Bp = B + (size_t)(bn + lr) * K + lcg;

    float acc[4][4][4];
#pragma unroll
    for (int mi = 0; mi < 4; mi++)
#pragma unroll
        for (int ni = 0; ni < 4; ni++)
#pragma unroll
            for (int r = 0; r < 4; r++) acc[mi][ni][r] = 0.0f;

    const int T = K / GBK;            // 24 for K=768

    // --- prologue: tile 0 into stage 0 ---
    {
        float4 av[4], bv[4];
#pragma unroll
        for (int q = 0; q < 4; q++) {
            av[q] = *(const float4*)(Ap + q * 4);
            bv[q] = *(const float4*)(Bp + q * 4);
        }
        uint32_t* S = smem32;
        split_store(S,              S + HSTAGE,     lr, pc, av);
        split_store(S + 2 * HSTAGE, S + 3 * HSTAGE, lr, pc, bv);
    }
    __syncthreads();

    int buf = 0;
    for (int t = 0; t < T; t++) {
        // register-prefetch next tile
        float4 av[4], bv[4];
        const bool have_next = (t + 1 < T);
        if (have_next) {
            const int k0 = (t + 1) * GBK;
#pragma unroll
            for (int q = 0; q < 4; q++) {
                av[q] = *(const float4*)(Ap + k0 + q * 4);
                bv[q] = *(const float4*)(Bp + k0 + q * 4);
            }
        }

        // compute on current stage
        const uint32_t* S   = smem32 + buf * 4 * HSTAGE;
        const uint32_t* Ahi = S;
        const uint32_t* Alo = S + HSTAGE;
        const uint32_t* Bhi = S + 2 * HSTAGE;
        const uint32_t* Blo = S + 3 * HSTAGE;

#pragma unroll
        for (int ks = 0; ks < 2; ks++) {
            const int pb = ks * 8;
            uint32_t bh[4][2], bl[4][2];
#pragma unroll
            for (int ni = 0; ni < 4; ni++) {
                const int nb = (wn * 32 + ni * 8 + gid) * KP + pb + tq;
                bh[ni][0] = Bhi[nb]; bh[ni][1] = Bhi[nb + 4];
                bl[ni][0] = Blo[nb]; bl[ni][1] = Blo[nb + 4];
            }
#pragma unroll
            for (int mi = 0; mi < 4; mi++) {
                const int mr = wm * 64 + mi * 16 + gid;
                const int a0 = mr * KP + pb + tq;
                const int a8 = (mr + 8) * KP + pb + tq;
                uint32_t ah[4], al[4];
                ah[0] = Ahi[a0]; ah[1] = Ahi[a8]; ah[2] = Ahi[a0 + 4]; ah[3] = Ahi[a8 + 4];
                al[0] = Alo[a0]; al[1] = Alo[a8]; al[2] = Alo[a0 + 4]; al[3] = Alo[a8 + 4];
#pragma unroll
                for (int ni = 0; ni < 4; ni++) {
                    mma16816(acc[mi][ni], ah, bh[ni]);   // hi*hi
                    mma16816(acc[mi][ni], ah, bl[ni]);   // hi*lo
                    mma16816(acc[mi][ni], al, bh[ni]);   // lo*hi
                }
            }
        }

        // store prefetched tile into other stage
        if (have_next) {
            uint32_t* D = smem32 + (buf ^ 1) * 4 * HSTAGE;
            split_store(D,              D + HSTAGE,     lr, pc, av);
            split_store(D + 2 * HSTAGE, D + 3 * HSTAGE, lr, pc, bv);
        }
        __syncthreads();
        buf ^= 1;
    }

    // --- epilogue: per-fragment float2 stores ---
#pragma unroll
    for (int mi = 0; mi < 4; mi++) {
        const int m0 = bm + wm * 64 + mi * 16 + gid;
#pragma unroll
        for (int ni = 0; ni < 4; ni++) {
            const int n0 = bn + wn * 32 + ni * 8 + 2 * tq;
            float2 r0 = make_float2(acc[mi][ni][0], acc[mi][ni][1]);  // row m0
            float2 r1 = make_float2(acc[mi][ni][2], acc[mi][ni][3]);  // row m0+8
            if (MODE == 0) {
                *(float2*)&C[(size_t)m0 * N + n0]       = r0;
                *(float2*)&C[(size_t)(m0 + 8) * N + n0] = r1;
            } else {
                const int h = n0 >> 6;
                const int e = n0 & (DHEAD - 1);
                {
                    const int b = m0 >> 11, p = m0 & (NCTX - 1);
                    *(float2*)&C[(((size_t)(b * HEADS + h)) * NCTX + p) * DHEAD + e] = r0;
                }
                {
                    const int m1 = m0 + 8;
                    const int b = m1 >> 11, p = m1 & (NCTX - 1);
                    *(float2*)&C[(((size_t)(b * HEADS + h)) * NCTX + p) * DHEAD + e] = r1;
                }
            }
        }
    }
}

// Fused QKV: gridDim.z selects which projection this CTA computes.
__global__ void __launch_bounds__(256)
qkv_gemm(const float* __restrict__ x,
         const float* __restrict__ Wq, const float* __restrict__ Wk,
         const float* __restrict__ Wv,
         float* __restrict__ Cq, float* __restrict__ Ck, float* __restrict__ Cv)
{
    const float* W = (blockIdx.z == 0) ? Wq : (blockIdx.z == 1) ? Wk : Wv;
    float* C       = (blockIdx.z == 0) ? Cq : (blockIdx.z == 1) ? Ck : Cv;
    bgemm_body<1>(x, W, C, MROWS, DMODEL, DMODEL);
}

__global__ void __launch_bounds__(256)
out_gemm(const float* __restrict__ A, const float* __restrict__ B,
         float* __restrict__ C)
{
    bgemm_body<0>(A, B, C, MROWS, DMODEL, DMODEL);
}

// ---------------------------------------------------------------------------
// Flash attention (fp32, causal) — unchanged from the 994.6us baseline.
// ---------------------------------------------------------------------------
#define SQ 68
#define QSCALE 0.125f   // 1/sqrt(64)

__global__ void __launch_bounds__(256)
flash_kernel(const float* __restrict__ Qg, const float* __restrict__ Kg,
             const float* __restrict__ Vg, float* __restrict__ Z)
{
    extern __shared__ float sm[];
    float* Qt = sm;                 // [64][SQ]  dim d, row r   (transposed)
    float* Kt = sm + 64 * SQ;       // [64][SQ]  dim d, key n   (transposed)
    float* Vs = sm + 2 * 64 * SQ;   // [64][SQ]  key n, dim d
    float* Ps = sm + 3 * 64 * SQ;   // [64][SQ]  row r, key n

    const int bh = blockIdx.y;
    const int b = bh / HEADS;
    const int h = bh - b * HEADS;
    const int qb = (int)gridDim.x - 1 - (int)blockIdx.x;   // heavy blocks first
    const int q0 = qb * 64;

    const float* Qb = Qg + (size_t)bh * NCTX * DHEAD;
    const float* Kb = Kg + (size_t)bh * NCTX * DHEAD;
    const float* Vb = Vg + (size_t)bh * NCTX * DHEAD;

    const int tid = threadIdx.x;
    const int tx = tid & 15;
    const int ty = tid >> 4;
    const int lr = tid >> 2;          // 0..63
    const int lc = (tid & 3) * 16;    // 0,16,32,48

    {
        const float4* src = (const float4*)(Qb + (size_t)(q0 + lr) * DHEAD + lc);
#pragma unroll
        for (int v = 0; v < 4; v++) {
            float4 q4 = src[v];
            const int c = lc + v * 4;
            Qt[(c + 0) * SQ + lr] = q4.x * QSCALE;
            Qt[(c + 1) * SQ + lr] = q4.y * QSCALE;
            Qt[(c + 2) * SQ + lr] = q4.z * QSCALE;
            Qt[(c + 3) * SQ + lr] = q4.w * QSCALE;
        }
    }

    float acc[4][4];
    float mrow[4], lrow[4];
#pragma unroll
    for (int i = 0; i < 4; i++) {
        mrow[i] = -1e30f; lrow[i] = 0.0f;
#pragma unroll
        for (int j = 0; j < 4; j++) acc[i][j] = 0.0f;
    }

    float4 kr[4], vr[4];
    {
        const float4* ks = (const float4*)(Kb + (size_t)lr * DHEAD + lc);
        const float4* vs = (const float4*)(Vb + (size_t)lr * DHEAD + lc);
#pragma unroll
        for (int v = 0; v < 4; v++) { kr[v] = ks[v]; vr[v] = vs[v]; }
    }

    for (int kb = 0; kb <= qb; kb++) {
#pragma unroll
        for (int v = 0; v < 4; v++) {
            const int c = lc + v * 4;
            Kt[(c + 0) * SQ + lr] = kr[v].x;
            Kt[(c + 1) * SQ + lr] = kr[v].y;
            Kt[(c + 2) * SQ + lr] = kr[v].z;
            Kt[(c + 3) * SQ + lr] = kr[v].w;
            *(float4*)&Vs[lr * SQ + c] = vr[v];
        }
        __syncthreads();   // (A)

        if (kb < qb) {
            const int nbase = (kb + 1) * 64;
            const float4* ks = (const float4*)(Kb + (size_t)(nbase + lr) * DHEAD + lc);
            const float4* vs = (const float4*)(Vb + (size_t)(nbase + lr) * DHEAD + lc);
#pragma unroll
            for (int v = 0; v < 4; v++) { kr[v] = ks[v]; vr[v] = vs[v]; }
        }

        float s[4][4];
#pragma unroll
        for (int i = 0; i < 4; i++)
#pragma unroll
            for (int j = 0; j < 4; j++) s[i][j] = 0.0f;
#pragma unroll
        for (int kk = 0; kk < 64; kk++) {
            float qa[4], kv[4];
            *(float4*)qa = *(const float4*)&Qt[kk * SQ + ty * 4];
            *(float4*)kv = *(const float4*)&Kt[kk * SQ + tx * 4];
#pragma unroll
            for (int i = 0; i < 4; i++)
#pragma unroll
                for (int j = 0; j < 4; j++)
                    s[i][j] = fmaf(qa[i], kv[j], s[i][j]);
        }

        if (kb == qb) {
            const int kbase = kb * 64;
#pragma unroll
            for (int i = 0; i < 4; i++) {
                const int qg = q0 + ty * 4 + i;
#pragma unroll
                for (int j = 0; j < 4; j++) {
                    if (kbase + tx * 4 + j > qg) s[i][j] = -1e30f;
                }
            }
        }

#pragma unroll
        for (int i = 0; i < 4; i++) {
            float mx = fmaxf(fmaxf(s[i][0], s[i][1]), fmaxf(s[i][2], s[i][3]));
#pragma unroll
            for (int o = 8; o >= 1; o >>= 1)
                mx = fmaxf(mx, __shfl_xor_sync(0xffffffffu, mx, o, 16));
            const float mnew = fmaxf(mrow[i], mx);
            const float alpha = __expf(mrow[i] - mnew);
            float psum = 0.0f;
#pragma unroll
            for (int j = 0; j < 4; j++) {
                const float p = __expf(s[i][j] - mnew);
                s[i][j] = p;
                psum += p;
            }
#pragma unroll
            for (int o = 8; o >= 1; o >>= 1)
                psum += __shfl_xor_sync(0xffffffffu, psum, o, 16);
            lrow[i] = lrow[i] * alpha + psum;
            mrow[i] = mnew;
#pragma unroll
            for (int j = 0; j < 4; j++) acc[i][j] *= alpha;
        }

#pragma unroll
        for (int i = 0; i < 4; i++)
            *(float4*)&Ps[(ty * 4 + i) * SQ + tx * 4] = *(float4*)s[i];
        __syncthreads();   // (B)

#pragma unroll
        for (int kk = 0; kk < 64; kk++) {
            float pr[4];
#pragma unroll
            for (int i = 0; i < 4; i++) pr[i] = Ps[(ty * 4 + i) * SQ + kk];
            float vv[4];
            *(float4*)vv = *(const float4*)&Vs[kk * SQ + tx * 4];
#pragma unroll
            for (int i = 0; i < 4; i++)
#pragma unroll
                for (int j = 0; j < 4; j++)
                    acc[i][j] = fmaf(pr[i], vv[j], acc[i][j]);
        }
        __syncthreads();   // (C)
    }

#pragma unroll
    for (int i = 0; i < 4; i++) {
        const int p = q0 + ty * 4 + i;
        const float rinv = 1.0f / lrow[i];
        float4 o4;
        o4.x = acc[i][0] * rinv;
        o4.y = acc[i][1] * rinv;
        o4.z = acc[i][2] * rinv;
        o4.w = acc[i][3] * rinv;
        *(float4*)&Z[((size_t)(b * NCTX + p)) * DMODEL + h * DHEAD + tx * 4] = o4;
    }
}

// ---------------------------------------------------------------------------
// Host launcher
// ---------------------------------------------------------------------------
extern "C" void kernel_launch(void* const* d_in, const int* in_sizes, int n_in,
                              void* d_out, int out_size)
{
    const float* x   = (const float*)d_in[0];
    const float* W_K = (const float*)d_in[1];
    const float* W_Q = (const float*)d_in[2];
    const float* W_V = (const float*)d_in[3];
    const float* W_O = (const float*)d_in[4];
    float* out = (float*)d_out;
    (void)in_sizes; (void)n_in; (void)out_size;

    float *qp, *kp, *vp, *zp;
    cudaGetSymbolAddress((void**)&qp, g_Q);
    cudaGetSymbolAddress((void**)&kp, g_K);
    cudaGetSymbolAddress((void**)&vp, g_V);
    cudaGetSymbolAddress((void**)&zp, g_Z);

    const int FLASH_SMEM = 4 * 64 * SQ * (int)sizeof(float);   // 69632 B
    cudaFuncSetAttribute(flash_kernel,
                         cudaFuncAttributeMaxDynamicSharedMemorySize, FLASH_SMEM);
    cudaFuncSetAttribute(qkv_gemm,
                         cudaFuncAttributeMaxDynamicSharedMemorySize, GSMEM_BYTES);
    cudaFuncSetAttribute(out_gemm,
                         cudaFuncAttributeMaxDynamicSharedMemorySize, GSMEM_BYTES);

    dim3 ggrid(MROWS / GBM, DMODEL / GBN);        // (32, 6)
    dim3 qkvgrid(MROWS / GBM, DMODEL / GBN, 3);   // (32, 6, 3) = 576 CTAs

    // Fused QKV projections (split-bf16 tensor cores, scatter into [B,H,P,64])
    qkv_gemm<<<qkvgrid, 256, GSMEM_BYTES>>>(x, W_Q, W_K, W_V, qp, kp, vp);

    // Fused causal attention -> head-major z_flat
    flash_kernel<<<dim3(NCTX / 64, BATCH * HEADS), 256, FLASH_SMEM>>>(qp, kp, vp, zp);

    // Output projection (split-bf16 tensor cores)
    out_gemm<<<ggrid, 256, GSMEM_BYTES>>>(zp, W_O, out);
}